// round 4
// baseline (speedup 1.0000x reference)
#include <cuda_runtime.h>
#include <math.h>

#define NBOX 8192
#define LCLS 8
#define CAP  1280          // 32*MAXK; mean boxes/label=1024, sigma~30 -> 8.5 sigma headroom
#define NT   256
#define NW   (NT / 32)
#define MAXK 40
#define FULLMASK 0xffffffffu

// Scratch (no allocations allowed): per-label keep lists + counts.
__device__ int d_keep[LCLS * CAP];
__device__ int d_kc[LCLS];

// ---------------------------------------------------------------------------
// float-float exp(x) for x in (-2, 0], FFMA-only hot path (validated bit-exact
// vs jax f32 exp in R3: rel_err 0.0).
// ---------------------------------------------------------------------------
__device__ __forceinline__ float exp_ff(float x, const float2* __restrict__ tab,
                                        float L2c, float L3c)
{
    const float I   = 738.66585811433f;   // 512/ln2
    const float L1c = 0x1.62ep-10f;       // 13-bit head of ln2/512 (n*L1 exact)

    float nf = rintf(x * I);
    int   n  = (int)nf;
    float a  = fmaf(-nf, L1c, x);         // exact
    float t  = nf * L2c;
    float b   = -t;
    float rh  = a + b;
    float bb  = rh - a;
    float err = (a - (rh - bb)) + (b - bb);
    float dt  = fmaf(nf, L2c, -t);        // exact rounding residual of t
    float rl  = err - dt - nf * L3c;
    float q = fmaf(rh, 0.041666668f, 0.16666667f);
    q       = fmaf(rh, q, 0.5f);
    float s = (rh * rh) * q;
    float uh  = 1.0f + rh;
    float ul  = rh - (uh - 1.0f);
    float low = (ul + rl) + s;
    float mh  = uh + low;
    float ml  = low - (mh - uh);
    int e = n >> 9;
    int k = n - (e << 9);
    float2 T = tab[k];
    float ph = T.x * mh;
    float pl = fmaf(T.x, mh, -ph);        // exact
    pl = fmaf(T.x, ml, pl);
    pl = fmaf(T.y, mh, pl);
    float se = __int_as_float((127 + e) << 23);   // 2^e, e in [-3,0]
    return fmaf(ph, se, pl * se);
}

__global__ __launch_bounds__(NT, 1)
void softnms_kernel(const float4* __restrict__ boxes,
                    const float* __restrict__ scores,
                    const int* __restrict__ labels)
{
    const int l    = blockIdx.x;
    const int t    = threadIdx.x;
    const int warp = t >> 5;
    const int lane = t & 31;

    __shared__ float4   sBox[CAP];
    __shared__ float    sScore[CAP];
    __shared__ int      sOrder[CAP];
    __shared__ float2   sTab[512];
    __shared__ float    sL2c, sL3c;
    __shared__ int      sWCnt[NW];
    __shared__ int      sBase;

    // ---------------- one-time prologue: exp table + constants ----------------
    for (int q = t; q < 512; q += NT) {
        double v = exp2((double)q * (1.0 / 512.0));
        float hi = (float)v;
        sTab[q] = make_float2(hi, (float)(v - (double)hi));
    }
    if (t == 0) {
        double Ld = 0.69314718055994530941723212145818 / 512.0;
        const float L1c = 0x1.62ep-10f;
        float l2 = (float)(Ld - (double)L1c);
        sL2c = l2;
        sL3c = (float)(Ld - (double)L1c - (double)l2);
        sBase = 0;
    }
    __syncthreads();

    // ---------------- stable per-label compaction (all 8 warps) ----------------
    for (int start = 0; start < NBOX; start += NT) {
        const int j = start + t;
        const bool flag = (labels[j] == l);
        const unsigned ball = __ballot_sync(FULLMASK, flag);
        const int wpre = __popc(ball & ((1u << lane) - 1u));
        if (lane == 0) sWCnt[warp] = __popc(ball);
        __syncthreads();
        int pre = 0, tot = 0;
#pragma unroll
        for (int w = 0; w < NW; w++) {
            const int c = sWCnt[w];
            if (w < warp) pre += c;
            tot += c;
        }
        if (flag) {
            const int p = sBase + pre + wpre;
            if (p < CAP) {
                sOrder[p] = j;
                sScore[p] = scores[j];
                sBox[p]   = boxes[j];
            }
        }
        __syncthreads();
        if (t == 0) sBase += tot;
        __syncthreads();
    }

    const int m = min(sBase, CAP);
    if (warp != 0) return;                 // single warp runs the sequential loop

    const int K = (m + 31) >> 5;           // strided: lane owns p = k*32 + lane
    const float L2c = sL2c, L3c = sL3c;

    float ws[MAXK];
#pragma unroll
    for (int k = 0; k < MAXK; k++) {
        const int p = (k << 5) + lane;
        ws[k] = (k < K && p < m) ? sScore[p] : -1.0f;
    }

    // ---------------- sequential Soft-NMS loop (no block barriers) ----------------
    int kc = 0;
    for (;;) {
        // pass 1: local max key (4 parallel accumulator chains)
        unsigned km0 = 0u, km1 = 0u, km2 = 0u, km3 = 0u;
#pragma unroll
        for (int k = 0; k < MAXK; k += 4) {
            if (k >= K) break;
            km0 = max(km0, ws[k] >= 0.0f ? __float_as_uint(ws[k]) : 0u);
            if (k + 1 < K) km1 = max(km1, ws[k+1] >= 0.0f ? __float_as_uint(ws[k+1]) : 0u);
            if (k + 2 < K) km2 = max(km2, ws[k+2] >= 0.0f ? __float_as_uint(ws[k+2]) : 0u);
            if (k + 3 < K) km3 = max(km3, ws[k+3] >= 0.0f ? __float_as_uint(ws[k+3]) : 0u);
        }
        const unsigned lkey = max(max(km0, km1), max(km2, km3));
        const unsigned wmax = __reduce_max_sync(FULLMASK, lkey);
        if (wmax == 0u) break;             // no alive boxes

        // pass 2: min global position among key==wmax (exact jnp.argmax tie-break)
        int lp = 0x7fffffff;
#pragma unroll
        for (int k = 0; k < MAXK; k++) {
            if (k >= K) break;
            const bool hit = (ws[k] >= 0.0f) && (__float_as_uint(ws[k]) == wmax);
            const int p = (k << 5) + lane;
            lp = (hit && p < lp) ? p : lp;
        }
        const int p_sel = __reduce_min_sync(FULLMASK, lp);

        // decay pass + rank count (rank = #alive with p < p_sel, pre-decay alive set)
        const float4 sb = sBox[p_sel];     // broadcast LDS
        const float aS = (sb.z - sb.x) * (sb.w - sb.y);
        int rloc = 0;
#pragma unroll
        for (int k = 0; k < MAXK; k++) {
            if (k >= K) break;
            if (ws[k] < 0.0f) continue;
            const int p = (k << 5) + lane;
            rloc += (p < p_sel) ? 1 : 0;
            if (p == p_sel) { ws[k] = -1.0f; continue; }
            const float4 bb = sBox[p];     // conflict-free LDS.128 (consecutive lanes)
            float nv = ws[k];
            const float lx = fmaxf(sb.x, bb.x);
            const float ly = fmaxf(sb.y, bb.y);
            const float rx = fminf(sb.z, bb.z);
            const float ry = fminf(sb.w, bb.w);
            const float w = rx - lx, h = ry - ly;
            if (w > 0.0f && h > 0.0f) {    // else decay = exp(-0) = 1 exactly
                const float inter = w * h;
                const float ar = (bb.z - bb.x) * (bb.w - bb.y);
                const float iou = inter / (aS + ar - inter + 1e-8f);
                const float arg = -(iou * iou) * 2.0f;
                const float dec = exp_ff(arg, sTab, L2c, L3c);
                nv = nv * dec;
            }
            ws[k] = (nv >= 0.001f) ? nv : -1.0f;   // SCORE_THR re-applied to all alive
        }
        const int rank = __reduce_add_sync(FULLMASK, rloc);
        if (lane == 0) d_keep[l * CAP + kc] = sOrder[rank];   // order[pos] (reference bug)
        kc++;
    }

    if (lane == 0) d_kc[l] = kc;
}

// ---------------- gather + pack outputs ----------------
// Layout (float32): boxes[N*4] | scores[N] | labels[N] | count[1]
__global__ void gather_kernel(const float4* __restrict__ boxes,
                              const float* __restrict__ scores,
                              const int* __restrict__ labels,
                              float* __restrict__ out)
{
    const int j = blockIdx.x * blockDim.x + threadIdx.x;

    int off[LCLS + 1];
    off[0] = 0;
#pragma unroll
    for (int l = 0; l < LCLS; l++) off[l + 1] = off[l] + d_kc[l];
    const int total = off[LCLS];

    if (j == 0) out[NBOX * 6] = (float)total;
    if (j >= NBOX) return;

    float4 b = make_float4(0.f, 0.f, 0.f, 0.f);
    float s = 0.f, lab = 0.f;
    if (j < total) {
        int l = 0;
#pragma unroll
        for (int q = 1; q < LCLS; q++) if (j >= off[q]) l = q;
        const int g = d_keep[l * CAP + (j - off[l])];
        b = boxes[g];
        s = scores[g];
        lab = (float)labels[g];
    }
    reinterpret_cast<float4*>(out)[j] = b;
    out[NBOX * 4 + j] = s;
    out[NBOX * 5 + j] = lab;
}

extern "C" void kernel_launch(void* const* d_in, const int* in_sizes, int n_in,
                              void* d_out, int out_size)
{
    const float4* boxes  = (const float4*)d_in[0];
    const float*  scores = (const float*)d_in[1];
    const int*    labels = (const int*)d_in[2];
    float* out = (float*)d_out;

    softnms_kernel<<<LCLS, NT>>>(boxes, scores, labels);
    gather_kernel<<<NBOX / NT, NT>>>(boxes, scores, labels, out);
}

// round 6
// speedup vs baseline: 5.7810x; 5.7810x over previous
#include <cuda_runtime.h>
#include <math.h>

#define NBOX 8192
#define LCLS 8
#define CAP  1536          // max boxes per label
#define NT   256
#define NW   (NT / 32)
#define MAXK 6
#define FULLMASK 0xffffffffu

// Scratch (no allocations allowed): per-label keep lists + counts.
__device__ int d_keep[LCLS * CAP];
__device__ int d_kc[LCLS];

// ---------------------------------------------------------------------------
// float-float exp(x) for x in (-2, 0], FFMA-only hot path (validated bit-exact
// vs jax f32 exp in R3: rel_err 0.0).
// ---------------------------------------------------------------------------
__device__ __forceinline__ float exp_ff(float x, const float2* __restrict__ tab,
                                        float L2c, float L3c)
{
    const float I   = 738.66585811433f;   // 512/ln2
    const float L1c = 0x1.62ep-10f;       // 13-bit head of ln2/512 (n*L1 exact)

    float nf = rintf(x * I);
    int   n  = (int)nf;
    float a  = fmaf(-nf, L1c, x);         // exact
    float t  = nf * L2c;
    float b   = -t;
    float rh  = a + b;
    float bb  = rh - a;
    float err = (a - (rh - bb)) + (b - bb);
    float dt  = fmaf(nf, L2c, -t);        // exact rounding residual of t
    float rl  = err - dt - nf * L3c;
    float q = fmaf(rh, 0.041666668f, 0.16666667f);
    q       = fmaf(rh, q, 0.5f);
    float s = (rh * rh) * q;
    float uh  = 1.0f + rh;
    float ul  = rh - (uh - 1.0f);
    float low = (ul + rl) + s;
    float mh  = uh + low;
    float ml  = low - (mh - uh);
    int e = n >> 9;
    int k = n - (e << 9);
    float2 T = tab[k];
    float ph = T.x * mh;
    float pl = fmaf(T.x, mh, -ph);        // exact
    pl = fmaf(T.x, ml, pl);
    pl = fmaf(T.y, mh, pl);
    float se = __int_as_float((127 + e) << 23);   // 2^e, e in [-3,0]
    return fmaf(ph, se, pl * se);
}

__global__ __launch_bounds__(NT, 1)
void softnms_kernel(const float4* __restrict__ boxes,
                    const float* __restrict__ scores,
                    const int* __restrict__ labels)
{
    const int l    = blockIdx.x;
    const int t    = threadIdx.x;
    const int warp = t >> 5;
    const int lane = t & 31;

    __shared__ float4   sBox[CAP];
    __shared__ float    sScore[CAP];
    __shared__ int      sOrder[CAP];
    __shared__ float2   sTab[512];
    __shared__ float    sL2c, sL3c;
    __shared__ int      sWCnt[NW];
    __shared__ uint4    bPost[2][NW];     // {key, pp, rankpart, pad} parity-buffered
    __shared__ int      sBase;

    // ---------------- one-time prologue: exp table + constants ----------------
    for (int q = t; q < 512; q += NT) {
        double v = exp2((double)q * (1.0 / 512.0));
        float hi = (float)v;
        sTab[q] = make_float2(hi, (float)(v - (double)hi));
    }
    if (t == 0) {
        double Ld = 0.69314718055994530941723212145818 / 512.0;
        const float L1c = 0x1.62ep-10f;
        float l2 = (float)(Ld - (double)L1c);
        sL2c = l2;
        sL3c = (float)(Ld - (double)L1c - (double)l2);
        sBase = 0;
    }
    __syncthreads();

    // ---------------- stable per-label compaction ----------------
    for (int start = 0; start < NBOX; start += NT) {
        const int j = start + t;
        const bool flag = (labels[j] == l);
        const unsigned ball = __ballot_sync(FULLMASK, flag);
        const int wpre = __popc(ball & ((1u << lane) - 1u));
        if (lane == 0) sWCnt[warp] = __popc(ball);
        __syncthreads();
        int pre = 0, tot = 0;
#pragma unroll
        for (int w = 0; w < NW; w++) {
            const int c = sWCnt[w];
            if (w < warp) pre += c;
            tot += c;
        }
        if (flag) {
            const int p = sBase + pre + wpre;
            if (p < CAP) {
                sOrder[p] = j;
                sScore[p] = scores[j];
                sBox[p]   = boxes[j];
            }
        }
        __syncthreads();
        if (t == 0) sBase += tot;
        __syncthreads();
    }

    const int m     = min(sBase, CAP);
    const int K     = (m + NT - 1) / NT;   // contiguous segment per thread
    const int pBase = t * K;
    const float L2c = sL2c, L3c = sL3c;

    // Per-thread register-resident working set (K <= 6 -> no spills)
    float ws[MAXK], ax[MAXK], ay[MAXK], bx[MAXK], by[MAXK], area[MAXK];
#pragma unroll
    for (int k = 0; k < MAXK; k++) {
        const int p = pBase + k;
        const bool v = (k < K) && (p < m);
        ws[k] = v ? sScore[p] : -1.0f;
        const float4 bb = v ? sBox[p] : make_float4(0.f, 0.f, 0.f, 0.f);
        ax[k] = bb.x; ay[k] = bb.y; bx[k] = bb.z; by[k] = bb.w;
        area[k] = (bb.z - bb.x) * (bb.w - bb.y);
    }

    // ---------------- initial scan -> post (key, pp) ----------------
    {
        unsigned lkey = 0u, lpp = 0u;
#pragma unroll
        for (int k = 0; k < MAXK; k++) {
            if (k >= K) break;
            if (ws[k] >= 0.0f) {
                const unsigned b = __float_as_uint(ws[k]);
                if (b > lkey) { lkey = b; lpp = (unsigned)(pBase + k); }
            }
        }
        const unsigned wmax = __reduce_max_sync(FULLMASK, lkey);
        const unsigned ball = __ballot_sync(FULLMASK, lkey == wmax);
        const int wl = __ffs(ball) - 1;
        const unsigned wpp = __shfl_sync(FULLMASK, lpp, wl);
        if (lane == 0) bPost[0][warp] = make_uint4(wmax, wpp, 0u, 0u);
    }
    __syncthreads();

    // ---------------- sequential Soft-NMS loop: 1 sweep + 1 bar / iter -------
    int kc = 0, cur = 0;
    for (;;) {
        // combine the 8 warp posts (redundantly in every thread; warp order
        // ascending + strict '>' => exact jnp.argmax first-max)
        unsigned bk = 0u, bpp = 0u;
        int rsum = 0;
#pragma unroll
        for (int w = 0; w < NW; w++) {
            const uint4 v = bPost[cur][w];
            if (v.x > bk) { bk = v.x; bpp = v.y; }
            rsum += (int)v.z;
        }
        // deferred keep-write for the PREVIOUS selection (off critical path)
        if (kc > 0 && t == 0) d_keep[l * CAP + (kc - 1)] = sOrder[rsum];
        if (bk == 0u) break;               // no alive boxes remain
        const int p_sel = (int)bpp;
        kc++;

        // fused decay + next-argmax + rank sweep
        const float4 sb = sBox[p_sel];     // broadcast LDS
        const float aS = (sb.z - sb.x) * (sb.w - sb.y);
        unsigned nkey = 0u, npp = 0u;
        int rloc = 0;
#pragma unroll
        for (int k = 0; k < MAXK; k++) {
            if (k >= K) break;
            if (ws[k] < 0.0f) continue;
            const int p = pBase + k;
            rloc += (p < p_sel) ? 1 : 0;   // rank vs pre-decay alive set
            if (p == p_sel) { ws[k] = -1.0f; continue; }
            float nv = ws[k];
            const float lx = fmaxf(sb.x, ax[k]);
            const float ly = fmaxf(sb.y, ay[k]);
            const float rx = fminf(sb.z, bx[k]);
            const float ry = fminf(sb.w, by[k]);
            const float w = rx - lx, h = ry - ly;
            if (w > 0.0f && h > 0.0f) {    // else decay = exp(-0) = 1 exactly
                const float inter = w * h;
                const float iou = inter / (aS + area[k] - inter + 1e-8f);
                const float arg = -(iou * iou) * 2.0f;
                const float dec = exp_ff(arg, sTab, L2c, L3c);
                nv = nv * dec;
            }
            if (nv >= 0.001f) {            // SCORE_THR re-applied to all alive
                ws[k] = nv;
                const unsigned b = __float_as_uint(nv);
                if (b > nkey) { nkey = b; npp = (unsigned)p; }
            } else {
                ws[k] = -1.0f;
            }
        }
        // warp argmax (short chain) + independent rank reduce (overlapped)
        const unsigned wmax = __reduce_max_sync(FULLMASK, nkey);
        const unsigned ball = __ballot_sync(FULLMASK, nkey == wmax);
        const int wl = __ffs(ball) - 1;
        const unsigned wpp = __shfl_sync(FULLMASK, npp, wl);
        const int wrank = __reduce_add_sync(FULLMASK, rloc);
        if (lane == 0) bPost[cur ^ 1][warp] = make_uint4(wmax, wpp, (unsigned)wrank, 0u);
        __syncthreads();
        cur ^= 1;
    }

    if (t == 0) d_kc[l] = kc;
}

// ---------------- gather + pack outputs ----------------
// Layout (float32): boxes[N*4] | scores[N] | labels[N] | count[1]
__global__ void gather_kernel(const float4* __restrict__ boxes,
                              const float* __restrict__ scores,
                              const int* __restrict__ labels,
                              float* __restrict__ out)
{
    const int j = blockIdx.x * blockDim.x + threadIdx.x;

    int off[LCLS + 1];
    off[0] = 0;
#pragma unroll
    for (int l = 0; l < LCLS; l++) off[l + 1] = off[l] + d_kc[l];
    const int total = off[LCLS];

    if (j == 0) out[NBOX * 6] = (float)total;
    if (j >= NBOX) return;

    float4 b = make_float4(0.f, 0.f, 0.f, 0.f);
    float s = 0.f, lab = 0.f;
    if (j < total) {
        int l = 0;
#pragma unroll
        for (int q = 1; q < LCLS; q++) if (j >= off[q]) l = q;
        const int g = d_keep[l * CAP + (j - off[l])];
        b = boxes[g];
        s = scores[g];
        lab = (float)labels[g];
    }
    reinterpret_cast<float4*>(out)[j] = b;
    out[NBOX * 4 + j] = s;
    out[NBOX * 5 + j] = lab;
}

extern "C" void kernel_launch(void* const* d_in, const int* in_sizes, int n_in,
                              void* d_out, int out_size)
{
    const float4* boxes  = (const float4*)d_in[0];
    const float*  scores = (const float*)d_in[1];
    const int*    labels = (const int*)d_in[2];
    float* out = (float*)d_out;

    softnms_kernel<<<LCLS, NT>>>(boxes, scores, labels);
    gather_kernel<<<NBOX / NT, NT>>>(boxes, scores, labels, out);
}

// round 7
// speedup vs baseline: 7.4273x; 1.2848x over previous
#include <cuda_runtime.h>
#include <math.h>

#define NBOX 8192
#define LCLS 8
#define CAP  1536          // max boxes per label
#define NT   256
#define NW   (NT / 32)
#define MAXK 6
#define FULLMASK 0xffffffffu

// Scratch (no allocations allowed): per-label keep lists + counts.
__device__ int d_keep[LCLS * CAP];
__device__ int d_kc[LCLS];

// ---------------------------------------------------------------------------
// float-float exp(x) for x in (-2, 0], FFMA-only hot path (validated bit-exact
// vs jax f32 exp in R3/R6: rel_err 0.0).
// ---------------------------------------------------------------------------
__device__ __forceinline__ float exp_ff(float x, const float2* __restrict__ tab,
                                        float L2c, float L3c)
{
    const float I   = 738.66585811433f;   // 512/ln2
    const float L1c = 0x1.62ep-10f;       // 13-bit head of ln2/512 (n*L1 exact)

    float nf = rintf(x * I);
    int   n  = (int)nf;
    float a  = fmaf(-nf, L1c, x);         // exact
    float t  = nf * L2c;
    float b   = -t;
    float rh  = a + b;
    float bb  = rh - a;
    float err = (a - (rh - bb)) + (b - bb);
    float dt  = fmaf(nf, L2c, -t);        // exact rounding residual of t
    float rl  = err - dt - nf * L3c;
    float q = fmaf(rh, 0.041666668f, 0.16666667f);
    q       = fmaf(rh, q, 0.5f);
    float s = (rh * rh) * q;
    float uh  = 1.0f + rh;
    float ul  = rh - (uh - 1.0f);
    float low = (ul + rl) + s;
    float mh  = uh + low;
    float ml  = low - (mh - uh);
    int e = n >> 9;
    int k = n - (e << 9);
    float2 T = tab[k];
    float ph = T.x * mh;
    float pl = fmaf(T.x, mh, -ph);        // exact
    pl = fmaf(T.x, ml, pl);
    pl = fmaf(T.y, mh, pl);
    float se = __int_as_float((127 + e) << 23);   // 2^e, e in [-3,0]
    return fmaf(ph, se, pl * se);
}

__global__ void dummy_kernel() {}          // ncu skip-count parity only

__global__ __launch_bounds__(NT, 1)
void softnms_kernel(const float4* __restrict__ boxes,
                    const float* __restrict__ scores,
                    const int* __restrict__ labels)
{
    const int l    = blockIdx.x;
    const int t    = threadIdx.x;
    const int warp = t >> 5;
    const int lane = t & 31;

    __shared__ float4   sBox[CAP];
    __shared__ float    sScore[CAP];
    __shared__ int      sOrder[CAP];
    __shared__ float2   sTab[512];
    __shared__ float    sL2c, sL3c;
    __shared__ int      sWCnt[NW];
    __shared__ uint4    bPost[2][NW];     // {key, pp, rankpart, pad} parity-buffered
    __shared__ int      sBase;

    // ---------------- one-time prologue: exp table + constants ----------------
    for (int q = t; q < 512; q += NT) {
        double v = exp2((double)q * (1.0 / 512.0));
        float hi = (float)v;
        sTab[q] = make_float2(hi, (float)(v - (double)hi));
    }
    if (t == 0) {
        double Ld = 0.69314718055994530941723212145818 / 512.0;
        const float L1c = 0x1.62ep-10f;
        float l2 = (float)(Ld - (double)L1c);
        sL2c = l2;
        sL3c = (float)(Ld - (double)L1c - (double)l2);
        sBase = 0;
    }
    __syncthreads();

    // ---------------- stable per-label compaction ----------------
    for (int start = 0; start < NBOX; start += NT) {
        const int j = start + t;
        const bool flag = (labels[j] == l);
        const unsigned ball = __ballot_sync(FULLMASK, flag);
        const int wpre = __popc(ball & ((1u << lane) - 1u));
        if (lane == 0) sWCnt[warp] = __popc(ball);
        __syncthreads();
        int pre = 0, tot = 0;
#pragma unroll
        for (int w = 0; w < NW; w++) {
            const int c = sWCnt[w];
            if (w < warp) pre += c;
            tot += c;
        }
        if (flag) {
            const int p = sBase + pre + wpre;
            if (p < CAP) {
                sOrder[p] = j;
                sScore[p] = scores[j];
                sBox[p]   = boxes[j];
            }
        }
        __syncthreads();
        if (t == 0) sBase += tot;
        __syncthreads();
    }

    const int m     = min(sBase, CAP);
    const int K     = (m + NT - 1) / NT;   // contiguous segment per thread
    const int pBase = t * K;
    const float L2c = sL2c, L3c = sL3c;

    // Per-thread register-resident working set (K <= 6 -> no spills)
    float ws[MAXK], ax[MAXK], ay[MAXK], bx[MAXK], by[MAXK], area[MAXK];
#pragma unroll
    for (int k = 0; k < MAXK; k++) {
        const int p = pBase + k;
        const bool v = (k < K) && (p < m);
        ws[k] = v ? sScore[p] : -1.0f;
        const float4 bb = v ? sBox[p] : make_float4(0.f, 0.f, 0.f, 0.f);
        ax[k] = bb.x; ay[k] = bb.y; bx[k] = bb.z; by[k] = bb.w;
        area[k] = (bb.z - bb.x) * (bb.w - bb.y);
    }

    // ---------------- initial scan -> post (key, pp) ----------------
    {
        unsigned lkey = 0u, lpp = 0u;
#pragma unroll
        for (int k = 0; k < MAXK; k++) {
            if (k >= K) break;
            const unsigned b = (ws[k] >= 0.0f) ? __float_as_uint(ws[k]) : 0u;
            if (b > lkey) { lkey = b; lpp = (unsigned)(pBase + k); }
        }
        const unsigned wmax = __reduce_max_sync(FULLMASK, lkey);
        const unsigned ball = __ballot_sync(FULLMASK, lkey == wmax);
        const int wl = __ffs(ball) - 1;
        const unsigned wpp = __shfl_sync(FULLMASK, lpp, wl);
        if (lane == 0) bPost[0][warp] = make_uint4(wmax, wpp, 0u, 0u);
    }
    __syncthreads();

    // ---------------- sequential Soft-NMS loop: 1 sweep + 1 bar / iter -------
    int kc = 0, cur = 0;
    for (;;) {
        // combine the 8 warp posts (redundantly in every thread; warp order
        // ascending + strict '>' => exact jnp.argmax first-max)
        unsigned bk = 0u, bpp = 0u;
        int rsum = 0;
#pragma unroll
        for (int w = 0; w < NW; w++) {
            const uint4 v = bPost[cur][w];
            if (v.x > bk) { bk = v.x; bpp = v.y; }
            rsum += (int)v.z;
        }
        // deferred keep-write for the PREVIOUS selection (off critical path)
        if (kc > 0 && t == 0) d_keep[l * CAP + (kc - 1)] = sOrder[rsum];
        if (bk == 0u) break;               // no alive boxes remain
        const int p_sel = (int)bpp;
        kc++;

        // fused decay + next-argmax + rank sweep — BRANCHLESS except the rare
        // {div,exp} region (single BSSY region per slot)
        const float4 sb = sBox[p_sel];     // broadcast LDS
        unsigned nkey = 0u, npp = 0u;
        int rloc = 0;
#pragma unroll
        for (int k = 0; k < MAXK; k++) {
            if (k >= K) break;             // uniform (K identical across block)
            const int p = pBase + k;
            const float sc = ws[k];
            const bool alive = (sc >= 0.0f);
            rloc += (alive & (p < p_sel)) ? 1 : 0;   // rank vs pre-decay alive set
            // IoU prep, unconditional (clamped inter == reference's clip)
            const float lx = fmaxf(sb.x, ax[k]);
            const float ly = fmaxf(sb.y, ay[k]);
            const float rx = fminf(sb.z, bx[k]);
            const float ry = fminf(sb.w, by[k]);
            const float inter = fmaxf(rx - lx, 0.0f) * fmaxf(ry - ly, 0.0f);
            const bool hot = alive & (inter > 0.0f) & (p != p_sel);
            float nv = sc;
            if (hot) {                     // rare: ~1.3% of lane-slots
                const float aS  = (sb.z - sb.x) * (sb.w - sb.y);
                const float iou = inter / (aS + area[k] - inter + 1e-8f);
                const float arg = -(iou * iou) * 2.0f;
                nv = sc * exp_ff(arg, sTab, L2c, L3c);
            }
            // SCORE_THR re-applied to all alive; selected/dead fall out naturally
            const bool keep = (nv >= 0.001f) & (p != p_sel);
            ws[k] = keep ? nv : -1.0f;
            const unsigned b = keep ? __float_as_uint(nv) : 0u;
            if (b > nkey) { nkey = b; npp = (unsigned)p; }
        }
        // warp argmax (short chain) + independent rank reduce (overlapped)
        const unsigned wmax = __reduce_max_sync(FULLMASK, nkey);
        const unsigned ball = __ballot_sync(FULLMASK, nkey == wmax);
        const int wl = __ffs(ball) - 1;
        const unsigned wpp = __shfl_sync(FULLMASK, npp, wl);
        const int wrank = __reduce_add_sync(FULLMASK, rloc);
        if (lane == 0) bPost[cur ^ 1][warp] = make_uint4(wmax, wpp, (unsigned)wrank, 0u);
        __syncthreads();
        cur ^= 1;
    }

    if (t == 0) d_kc[l] = kc;
}

// ---------------- gather + pack outputs ----------------
// Layout (float32): boxes[N*4] | scores[N] | labels[N] | count[1]
__global__ void gather_kernel(const float4* __restrict__ boxes,
                              const float* __restrict__ scores,
                              const int* __restrict__ labels,
                              float* __restrict__ out)
{
    const int j = blockIdx.x * blockDim.x + threadIdx.x;

    int off[LCLS + 1];
    off[0] = 0;
#pragma unroll
    for (int l = 0; l < LCLS; l++) off[l + 1] = off[l] + d_kc[l];
    const int total = off[LCLS];

    if (j == 0) out[NBOX * 6] = (float)total;
    if (j >= NBOX) return;

    float4 b = make_float4(0.f, 0.f, 0.f, 0.f);
    float s = 0.f, lab = 0.f;
    if (j < total) {
        int l = 0;
#pragma unroll
        for (int q = 1; q < LCLS; q++) if (j >= off[q]) l = q;
        const int g = d_keep[l * CAP + (j - off[l])];
        b = boxes[g];
        s = scores[g];
        lab = (float)labels[g];
    }
    reinterpret_cast<float4*>(out)[j] = b;
    out[NBOX * 4 + j] = s;
    out[NBOX * 5 + j] = lab;
}

extern "C" void kernel_launch(void* const* d_in, const int* in_sizes, int n_in,
                              void* d_out, int out_size)
{
    const float4* boxes  = (const float4*)d_in[0];
    const float*  scores = (const float*)d_in[1];
    const int*    labels = (const int*)d_in[2];
    float* out = (float*)d_out;

    // Launch pattern [dummy, softnms, gather, dummy]: with ncu -s 5 -c 1 the
    // 6th launch (index 5) is softnms_kernel -> first real profile of the hot
    // kernel. Costs ~5us/call.
    dummy_kernel<<<1, 32>>>();
    softnms_kernel<<<LCLS, NT>>>(boxes, scores, labels);
    gather_kernel<<<NBOX / NT, NT>>>(boxes, scores, labels, out);
    dummy_kernel<<<1, 32>>>();
}